// round 1
// baseline (speedup 1.0000x reference)
#include <cuda_runtime.h>
#include <cuda_bf16.h>

// Problem constants
#define NN 100000
#define EE 1000000
#define DD 64

// Scratch (device globals; no allocation allowed)
__device__ float g_dis[NN];        // deg -> rsqrt(deg)
__device__ float g_norm[EE];       // dis[src]*dis[dst]
__device__ float g_h[NN * DD];     // h = x @ W (current layer)
__device__ float g_buf[NN * DD];   // layer-1 aggregation target (pre-relu output)

// ---------------------------------------------------------------------------
// 1) deg init: deg[i] = 1 (self loop)
__global__ void k_init_deg() {
    int i = blockIdx.x * blockDim.x + threadIdx.x;
    if (i < NN) g_dis[i] = 1.0f;
}

// 2) deg count: deg[dst[e]] += 1
__global__ void k_count_deg(const int* __restrict__ ei) {
    int e = blockIdx.x * blockDim.x + threadIdx.x;
    if (e < EE) {
        int d = __ldg(&ei[EE + e]);
        asm volatile("red.global.add.f32 [%0], %1;" :: "l"(&g_dis[d]), "f"(1.0f) : "memory");
    }
}

// 3) dis[i] = rsqrt(deg[i])
__global__ void k_rsqrt() {
    int i = blockIdx.x * blockDim.x + threadIdx.x;
    if (i < NN) g_dis[i] = rsqrtf(g_dis[i]);
}

// 4) norm[e] = dis[src]*dis[dst]
__global__ void k_norm(const int* __restrict__ ei) {
    int e = blockIdx.x * blockDim.x + threadIdx.x;
    if (e < EE) {
        int s = __ldg(&ei[e]);
        int d = __ldg(&ei[EE + e]);
        g_norm[e] = g_dis[s] * g_dis[d];
    }
}

// ---------------------------------------------------------------------------
// GEMM: H = act(X) @ W  (X: [N,64], W: [64,64])
// Also initializes BUF = H * dis^2 + b  (self-loop + bias), the scatter target.
// Block: 256 threads, 64 rows x 64 cols per block, 4x4 microtile per thread.
template <bool RELU_ON_LOAD>
__global__ void k_gemm(const float* __restrict__ X, const float* __restrict__ W,
                       const float* __restrict__ b,
                       float* __restrict__ H, float* __restrict__ BUF) {
    __shared__ float Ws[64][64];      // Ws[k][col]
    __shared__ float Xs[64][68];      // Xs[k][row_local], padded to 68 (16B-aligned rows)

    const int tid = threadIdx.x;              // 0..255
    const int rowBase = blockIdx.x * 64;

    // load W (4096 floats)
    #pragma unroll
    for (int i = tid; i < 64 * 64; i += 256)
        Ws[i >> 6][i & 63] = W[i];

    // load X tile transposed: thread reads X[row][k] with k = tid&63, rows stride 4
    {
        const int k = tid & 63;
        #pragma unroll
        for (int r = (tid >> 6); r < 64; r += 4) {
            int row = rowBase + r;
            float v = 0.0f;
            if (row < NN) {
                v = X[row * DD + k];
                if (RELU_ON_LOAD) v = fmaxf(v, 0.0f);
            }
            Xs[k][r] = v;
        }
    }
    __syncthreads();

    const int rg = (tid >> 4) << 2;   // row group: 0,4,...,60
    const int cg = (tid & 15) << 2;   // col group: 0,4,...,60

    float acc[4][4];
    #pragma unroll
    for (int i = 0; i < 4; i++)
        #pragma unroll
        for (int j = 0; j < 4; j++) acc[i][j] = 0.0f;

    #pragma unroll 8
    for (int k = 0; k < 64; k++) {
        float4 xv = *(const float4*)&Xs[k][rg];
        float4 wv = *(const float4*)&Ws[k][cg];
        acc[0][0] += xv.x * wv.x; acc[0][1] += xv.x * wv.y; acc[0][2] += xv.x * wv.z; acc[0][3] += xv.x * wv.w;
        acc[1][0] += xv.y * wv.x; acc[1][1] += xv.y * wv.y; acc[1][2] += xv.y * wv.z; acc[1][3] += xv.y * wv.w;
        acc[2][0] += xv.z * wv.x; acc[2][1] += xv.z * wv.y; acc[2][2] += xv.z * wv.z; acc[2][3] += xv.z * wv.w;
        acc[3][0] += xv.w * wv.x; acc[3][1] += xv.w * wv.y; acc[3][2] += xv.w * wv.z; acc[3][3] += xv.w * wv.w;
    }

    // epilogue: write H and BUF = H*dis^2 + b
    float4 bv = *(const float4*)&b[cg];
    #pragma unroll
    for (int i = 0; i < 4; i++) {
        int row = rowBase + rg + i;
        if (row >= NN) break;
        float ds = g_dis[row];
        float d2 = ds * ds;
        float4 hv;
        hv.x = acc[i][0]; hv.y = acc[i][1]; hv.z = acc[i][2]; hv.w = acc[i][3];
        *(float4*)&H[row * DD + cg] = hv;
        float4 sv;
        sv.x = hv.x * d2 + bv.x; sv.y = hv.y * d2 + bv.y;
        sv.z = hv.z * d2 + bv.z; sv.w = hv.w * d2 + bv.w;
        *(float4*)&BUF[row * DD + cg] = sv;
    }
}

// ---------------------------------------------------------------------------
// Edge aggregation: OUT[dst] += norm[e] * H[src], vectorized float4,
// 16 threads per edge (one float4 chunk each), red.global.add.v4.f32.
__global__ void k_edge(const float* __restrict__ H, float* __restrict__ OUT,
                       const int* __restrict__ ei) {
    int gid = blockIdx.x * blockDim.x + threadIdx.x;
    if (gid >= EE * 16) return;
    int e = gid >> 4;
    int c = (gid & 15) << 2;          // column offset 0,4,...,60
    int s = __ldg(&ei[e]);
    int d = __ldg(&ei[EE + e]);
    float nrm = __ldg(&g_norm[e]);
    float4 v = *(const float4*)&H[s * DD + c];
    v.x *= nrm; v.y *= nrm; v.z *= nrm; v.w *= nrm;
    float* p = &OUT[d * DD + c];
    asm volatile("red.global.add.v4.f32 [%0], {%1, %2, %3, %4};"
                 :: "l"(p), "f"(v.x), "f"(v.y), "f"(v.z), "f"(v.w) : "memory");
}

// ---------------------------------------------------------------------------
extern "C" void kernel_launch(void* const* d_in, const int* in_sizes, int n_in,
                              void* d_out, int out_size) {
    const float* x  = (const float*)d_in[0];
    const int*   ei = (const int*)d_in[1];
    const float* W1 = (const float*)d_in[2];
    const float* b1 = (const float*)d_in[3];
    const float* W2 = (const float*)d_in[4];
    const float* b2 = (const float*)d_in[5];
    float* out = (float*)d_out;

    float* dH;   cudaGetSymbolAddress((void**)&dH,   g_h);
    float* dBuf; cudaGetSymbolAddress((void**)&dBuf, g_buf);

    const int TB = 256;
    const int gN = (NN + TB - 1) / TB;
    const int gE = (EE + TB - 1) / TB;
    const int gE16 = (EE * 16 + TB - 1) / TB;
    const int gG = (NN + 63) / 64;

    // degree / norm (shared by both layers)
    k_init_deg<<<gN, TB>>>();
    k_count_deg<<<gE, TB>>>(ei);
    k_rsqrt<<<gN, TB>>>();
    k_norm<<<gE, TB>>>(ei);

    // Layer 1: h1 = x@W1 ; buf = h1*dis^2 + b1 ; buf += scatter(norm*h1[src])
    k_gemm<false><<<gG, TB>>>(x, W1, b1, dH, dBuf);
    k_edge<<<gE16, TB>>>(dH, dBuf, ei);

    // Layer 2: h2 = relu(buf)@W2 ; out = h2*dis^2 + b2 ; out += scatter(norm*h2[src])
    k_gemm<true><<<gG, TB>>>(dBuf, W2, b2, dH, out);
    k_edge<<<gE16, TB>>>(dH, out, ei);
}

// round 2
// speedup vs baseline: 1.2575x; 1.2575x over previous
#include <cuda_runtime.h>
#include <cuda_bf16.h>

// Problem constants
#define NN 100000
#define EE 1000000
#define DD 64

#define SCAN_CHUNK 1024
#define NB ((NN + SCAN_CHUNK - 1) / SCAN_CHUNK)   // 98 blocks

// Scratch (device globals; no allocation allowed)
__device__ int   g_deg[NN];          // in-degree (excl self loop)
__device__ int   g_rowptr[NN + 1];   // CSR row pointers
__device__ int   g_cursor[NN];       // scatter cursors
__device__ float g_dis[NN];          // rsqrt(deg+1)
__device__ int   g_src[EE];          // CSR: source node per slot
__device__ float g_wgt[EE];          // CSR: edge norm per slot
__device__ int   g_bsum[NB];         // scan block sums
__device__ int   g_bofs[NB];         // scan block offsets
__device__ float g_h[NN * DD];       // h = act(X) @ W
__device__ float g_buf[NN * DD];     // layer-1 output buffer

// ---------------------------------------------------------------------------
// 1) zero degree
__global__ void k_zero_deg() {
    int i = blockIdx.x * blockDim.x + threadIdx.x;
    if (i < NN) g_deg[i] = 0;
}

// 2) histogram: deg[dst]++
__global__ void k_hist(const int* __restrict__ ei) {
    int e = blockIdx.x * blockDim.x + threadIdx.x;
    if (e < EE) {
        int d = __ldg(&ei[EE + e]);
        atomicAdd(&g_deg[d], 1);
    }
}

// 3a) per-block partial sums (1024 elems / block)
__global__ void k_scan_part() {
    __shared__ int sdata[256];
    int base = blockIdx.x * SCAN_CHUNK;
    int sum = 0;
    for (int i = threadIdx.x; i < SCAN_CHUNK; i += 256) {
        int idx = base + i;
        if (idx < NN) sum += g_deg[idx];
    }
    sdata[threadIdx.x] = sum;
    __syncthreads();
    for (int s = 128; s > 0; s >>= 1) {
        if (threadIdx.x < s) sdata[threadIdx.x] += sdata[threadIdx.x + s];
        __syncthreads();
    }
    if (threadIdx.x == 0) g_bsum[blockIdx.x] = sdata[0];
}

// 3b) scan the block sums (NB <= 128), single block
__global__ void k_scan_mid() {
    __shared__ int s[128];
    int tid = threadIdx.x;
    int v = (tid < NB) ? g_bsum[tid] : 0;
    s[tid] = v;
    __syncthreads();
    for (int off = 1; off < 128; off <<= 1) {
        int t = (tid >= off) ? s[tid - off] : 0;
        __syncthreads();
        s[tid] += t;
        __syncthreads();
    }
    if (tid < NB) g_bofs[tid] = s[tid] - v;   // exclusive
    if (tid == 0) g_rowptr[NN] = EE;
}

// 3c) final: block-local exclusive scan + offset; also cursor copy + dis
__global__ void k_scan_final() {
    const int tid = threadIdx.x;
    const int base = blockIdx.x * SCAN_CHUNK;
    int v[4];
    int tsum = 0;
    #pragma unroll
    for (int j = 0; j < 4; j++) {
        int idx = base + tid * 4 + j;
        v[j] = (idx < NN) ? g_deg[idx] : 0;
        tsum += v[j];
    }
    // warp inclusive scan of tsum
    int lane = tid & 31, wid = tid >> 5;
    int x = tsum;
    #pragma unroll
    for (int off = 1; off < 32; off <<= 1) {
        int y = __shfl_up_sync(0xFFFFFFFFu, x, off);
        if (lane >= off) x += y;
    }
    __shared__ int wsum[8], wofs[8];
    if (lane == 31) wsum[wid] = x;
    __syncthreads();
    if (tid == 0) {
        int run = 0;
        #pragma unroll
        for (int w = 0; w < 8; w++) { wofs[w] = run; run += wsum[w]; }
    }
    __syncthreads();
    int excl = x - tsum + wofs[wid] + g_bofs[blockIdx.x];
    #pragma unroll
    for (int j = 0; j < 4; j++) {
        int idx = base + tid * 4 + j;
        if (idx < NN) {
            g_rowptr[idx] = excl;
            g_cursor[idx] = excl;
            g_dis[idx] = rsqrtf((float)(v[j] + 1));
        }
        excl += v[j];
    }
}

// 4) build CSR: slot = cursor[dst]++; store {src, norm}
__global__ void k_build(const int* __restrict__ ei) {
    int e = blockIdx.x * blockDim.x + threadIdx.x;
    if (e < EE) {
        int s = __ldg(&ei[e]);
        int d = __ldg(&ei[EE + e]);
        float w = g_dis[s] * g_dis[d];
        int pos = atomicAdd(&g_cursor[d], 1);
        g_src[pos] = s;
        g_wgt[pos] = w;
    }
}

// ---------------------------------------------------------------------------
// GEMM: H = act(X) @ W  (X: [N,64], W: [64,64])
// Also initializes BUF = H * dis^2 + b  (self-loop + bias), the agg target.
template <bool RELU_ON_LOAD>
__global__ void k_gemm(const float* __restrict__ X, const float* __restrict__ W,
                       const float* __restrict__ b,
                       float* __restrict__ H, float* __restrict__ BUF) {
    __shared__ float Ws[64][64];
    __shared__ float Xs[64][68];

    const int tid = threadIdx.x;
    const int rowBase = blockIdx.x * 64;

    #pragma unroll
    for (int i = tid; i < 64 * 64; i += 256)
        Ws[i >> 6][i & 63] = W[i];

    {
        const int k = tid & 63;
        #pragma unroll
        for (int r = (tid >> 6); r < 64; r += 4) {
            int row = rowBase + r;
            float v = 0.0f;
            if (row < NN) {
                v = X[row * DD + k];
                if (RELU_ON_LOAD) v = fmaxf(v, 0.0f);
            }
            Xs[k][r] = v;
        }
    }
    __syncthreads();

    const int rg = (tid >> 4) << 2;
    const int cg = (tid & 15) << 2;

    float acc[4][4];
    #pragma unroll
    for (int i = 0; i < 4; i++)
        #pragma unroll
        for (int j = 0; j < 4; j++) acc[i][j] = 0.0f;

    #pragma unroll 8
    for (int k = 0; k < 64; k++) {
        float4 xv = *(const float4*)&Xs[k][rg];
        float4 wv = *(const float4*)&Ws[k][cg];
        acc[0][0] += xv.x * wv.x; acc[0][1] += xv.x * wv.y; acc[0][2] += xv.x * wv.z; acc[0][3] += xv.x * wv.w;
        acc[1][0] += xv.y * wv.x; acc[1][1] += xv.y * wv.y; acc[1][2] += xv.y * wv.z; acc[1][3] += xv.y * wv.w;
        acc[2][0] += xv.z * wv.x; acc[2][1] += xv.z * wv.y; acc[2][2] += xv.z * wv.z; acc[2][3] += xv.z * wv.w;
        acc[3][0] += xv.w * wv.x; acc[3][1] += xv.w * wv.y; acc[3][2] += xv.w * wv.z; acc[3][3] += xv.w * wv.w;
    }

    float4 bv = *(const float4*)&b[cg];
    #pragma unroll
    for (int i = 0; i < 4; i++) {
        int row = rowBase + rg + i;
        if (row >= NN) break;
        float ds = g_dis[row];
        float d2 = ds * ds;
        float4 hv;
        hv.x = acc[i][0]; hv.y = acc[i][1]; hv.z = acc[i][2]; hv.w = acc[i][3];
        *(float4*)&H[row * DD + cg] = hv;
        float4 sv;
        sv.x = hv.x * d2 + bv.x; sv.y = hv.y * d2 + bv.y;
        sv.z = hv.z * d2 + bv.z; sv.w = hv.w * d2 + bv.w;
        *(float4*)&BUF[row * DD + cg] = sv;
    }
}

// ---------------------------------------------------------------------------
// Pull aggregation: one warp per dst node. acc = sum_e w[e] * H[src[e]];
// OUT[n] += acc (OUT pre-initialized with self-loop + bias by gemm epilogue).
__global__ void k_agg(const float* __restrict__ H, float* __restrict__ OUT) {
    int warp = (blockIdx.x * blockDim.x + threadIdx.x) >> 5;
    int lane = threadIdx.x & 31;
    if (warp >= NN) return;

    int beg = __ldg(&g_rowptr[warp]);
    int end = __ldg(&g_rowptr[warp + 1]);
    const int c = lane * 2;

    float ax = 0.0f, ay = 0.0f;
    int e = beg;
    // 2-edge unroll for MLP
    for (; e + 1 < end; e += 2) {
        int s0 = __ldg(&g_src[e]);     float w0 = __ldg(&g_wgt[e]);
        int s1 = __ldg(&g_src[e + 1]); float w1 = __ldg(&g_wgt[e + 1]);
        float2 h0 = *(const float2*)&H[s0 * DD + c];
        float2 h1 = *(const float2*)&H[s1 * DD + c];
        ax += w0 * h0.x + w1 * h1.x;
        ay += w0 * h0.y + w1 * h1.y;
    }
    if (e < end) {
        int s0 = __ldg(&g_src[e]); float w0 = __ldg(&g_wgt[e]);
        float2 h0 = *(const float2*)&H[s0 * DD + c];
        ax += w0 * h0.x;
        ay += w0 * h0.y;
    }

    float2 o = *(float2*)&OUT[warp * DD + c];
    o.x += ax; o.y += ay;
    *(float2*)&OUT[warp * DD + c] = o;
}

// ---------------------------------------------------------------------------
extern "C" void kernel_launch(void* const* d_in, const int* in_sizes, int n_in,
                              void* d_out, int out_size) {
    const float* x  = (const float*)d_in[0];
    const int*   ei = (const int*)d_in[1];
    const float* W1 = (const float*)d_in[2];
    const float* b1 = (const float*)d_in[3];
    const float* W2 = (const float*)d_in[4];
    const float* b2 = (const float*)d_in[5];
    float* out = (float*)d_out;

    float* dH;   cudaGetSymbolAddress((void**)&dH,   g_h);
    float* dBuf; cudaGetSymbolAddress((void**)&dBuf, g_buf);

    const int TB = 256;
    const int gN = (NN + TB - 1) / TB;
    const int gE = (EE + TB - 1) / TB;
    const int gG = (NN + 63) / 64;
    const int gA = (NN * 32 + TB - 1) / TB;   // warp per node

    // CSR + norm setup (shared by both layers)
    k_zero_deg<<<gN, TB>>>();
    k_hist<<<gE, TB>>>(ei);
    k_scan_part<<<NB, 256>>>();
    k_scan_mid<<<1, 128>>>();
    k_scan_final<<<NB, 256>>>();
    k_build<<<gE, TB>>>(ei);

    // Layer 1: h1 = x@W1 ; buf = h1*dis^2 + b1 ; buf += pull-agg(norm*h1[src])
    k_gemm<false><<<gG, TB>>>(x, W1, b1, dH, dBuf);
    k_agg<<<gA, TB>>>(dH, dBuf);

    // Layer 2: h2 = relu(buf)@W2 ; out = h2*dis^2 + b2 ; out += pull-agg
    k_gemm<true><<<gG, TB>>>(dBuf, W2, b2, dH, out);
    k_agg<<<gA, TB>>>(dH, out);
}

// round 3
// speedup vs baseline: 1.4000x; 1.1133x over previous
#include <cuda_runtime.h>
#include <cuda_bf16.h>

#define NN 100000
#define EE 1000000
#define DD 64

#define SCAN_CHUNK 1024
#define NB ((NN + SCAN_CHUNK - 1) / SCAN_CHUNK)   // 98 blocks

// Scratch (device globals; no allocation allowed)
__device__ int   g_deg[NN];          // in-degree (excl self loop)
__device__ int   g_rowptr[NN];       // CSR bucket start (arrival-order bases)
__device__ float g_dis[NN];          // rsqrt(deg+1)
__device__ int   g_rank[EE];         // per-edge rank within dst bucket
__device__ int   g_src[EE];          // CSR: source node per slot
__device__ int   g_ctr;              // arrival-order base counter
__device__ float g_h[NN * DD];       // h = act(X) @ W
__device__ float g_buf[NN * DD];     // layer-1 output buffer

// ---------------------------------------------------------------------------
// hist: rank[e] = deg[dst]++  (4 edges per thread, vectorized)
__global__ void k_hist(const int* __restrict__ ei) {
    int t = blockIdx.x * blockDim.x + threadIdx.x;
    int e = t * 4;
    if (e + 3 < EE) {
        int4 d = *(const int4*)&ei[EE + e];
        int4 r;
        r.x = atomicAdd(&g_deg[d.x], 1);
        r.y = atomicAdd(&g_deg[d.y], 1);
        r.z = atomicAdd(&g_deg[d.z], 1);
        r.w = atomicAdd(&g_deg[d.w], 1);
        *(int4*)&g_rank[e] = r;
    } else {
        for (; e < EE; e++) {
            int d = __ldg(&ei[EE + e]);
            g_rank[e] = atomicAdd(&g_deg[d], 1);
        }
    }
}

// ---------------------------------------------------------------------------
// one-kernel bucket assignment: block-local scan + atomic base (arrival order).
// Buckets are disjoint & contiguous; monotonicity across blocks not needed.
// Also computes dis = rsqrt(deg+1).
__global__ void k_buckets() {
    const int tid = threadIdx.x;
    const int base = blockIdx.x * SCAN_CHUNK;
    int v[4];
    int tsum = 0;
    #pragma unroll
    for (int j = 0; j < 4; j++) {
        int idx = base + tid * 4 + j;
        v[j] = (idx < NN) ? g_deg[idx] : 0;
        tsum += v[j];
    }
    // warp inclusive scan of tsum
    int lane = tid & 31, wid = tid >> 5;
    int x = tsum;
    #pragma unroll
    for (int off = 1; off < 32; off <<= 1) {
        int y = __shfl_up_sync(0xFFFFFFFFu, x, off);
        if (lane >= off) x += y;
    }
    __shared__ int wsum[8], wofs[8];
    __shared__ int sbase;
    if (lane == 31) wsum[wid] = x;
    __syncthreads();
    if (tid == 0) {
        int run = 0;
        #pragma unroll
        for (int w = 0; w < 8; w++) { wofs[w] = run; run += wsum[w]; }
        sbase = atomicAdd(&g_ctr, run);      // block's bucket base, arrival order
    }
    __syncthreads();
    int excl = sbase + wofs[wid] + (x - tsum);
    #pragma unroll
    for (int j = 0; j < 4; j++) {
        int idx = base + tid * 4 + j;
        if (idx < NN) {
            g_rowptr[idx] = excl;
            g_dis[idx] = rsqrtf((float)(v[j] + 1));
        }
        excl += v[j];
    }
}

// ---------------------------------------------------------------------------
// build (atomic-free): src[rowptr[dst] + rank[e]] = src_node
__global__ void k_build(const int* __restrict__ ei) {
    int t = blockIdx.x * blockDim.x + threadIdx.x;
    int e = t * 4;
    if (e + 3 < EE) {
        int4 s = *(const int4*)&ei[e];
        int4 d = *(const int4*)&ei[EE + e];
        int4 r = *(const int4*)&g_rank[e];
        g_src[__ldg(&g_rowptr[d.x]) + r.x] = s.x;
        g_src[__ldg(&g_rowptr[d.y]) + r.y] = s.y;
        g_src[__ldg(&g_rowptr[d.z]) + r.z] = s.z;
        g_src[__ldg(&g_rowptr[d.w]) + r.w] = s.w;
    } else {
        for (; e < EE; e++) {
            int s = __ldg(&ei[e]);
            int d = __ldg(&ei[EE + e]);
            g_src[__ldg(&g_rowptr[d]) + __ldg(&g_rank[e])] = s;
        }
    }
}

// ---------------------------------------------------------------------------
// GEMM: H = act(X) @ W  (X: [N,64], W: [64,64]). Writes H only.
template <bool RELU_ON_LOAD>
__global__ void k_gemm(const float* __restrict__ X, const float* __restrict__ W,
                       float* __restrict__ H) {
    __shared__ float Ws[64][64];
    __shared__ float Xs[64][68];

    const int tid = threadIdx.x;
    const int rowBase = blockIdx.x * 64;

    #pragma unroll
    for (int i = tid; i < 64 * 64; i += 256)
        Ws[i >> 6][i & 63] = W[i];

    {
        const int k = tid & 63;
        #pragma unroll
        for (int r = (tid >> 6); r < 64; r += 4) {
            int row = rowBase + r;
            float v = 0.0f;
            if (row < NN) {
                v = X[row * DD + k];
                if (RELU_ON_LOAD) v = fmaxf(v, 0.0f);
            }
            Xs[k][r] = v;
        }
    }
    __syncthreads();

    const int rg = (tid >> 4) << 2;
    const int cg = (tid & 15) << 2;

    float acc[4][4];
    #pragma unroll
    for (int i = 0; i < 4; i++)
        #pragma unroll
        for (int j = 0; j < 4; j++) acc[i][j] = 0.0f;

    #pragma unroll 8
    for (int k = 0; k < 64; k++) {
        float4 xv = *(const float4*)&Xs[k][rg];
        float4 wv = *(const float4*)&Ws[k][cg];
        acc[0][0] += xv.x * wv.x; acc[0][1] += xv.x * wv.y; acc[0][2] += xv.x * wv.z; acc[0][3] += xv.x * wv.w;
        acc[1][0] += xv.y * wv.x; acc[1][1] += xv.y * wv.y; acc[1][2] += xv.y * wv.z; acc[1][3] += xv.y * wv.w;
        acc[2][0] += xv.z * wv.x; acc[2][1] += xv.z * wv.y; acc[2][2] += xv.z * wv.z; acc[2][3] += xv.z * wv.w;
        acc[3][0] += xv.w * wv.x; acc[3][1] += xv.w * wv.y; acc[3][2] += xv.w * wv.z; acc[3][3] += xv.w * wv.w;
    }

    #pragma unroll
    for (int i = 0; i < 4; i++) {
        int row = rowBase + rg + i;
        if (row >= NN) break;
        float4 hv;
        hv.x = acc[i][0]; hv.y = acc[i][1]; hv.z = acc[i][2]; hv.w = acc[i][3];
        *(float4*)&H[row * DD + cg] = hv;
    }
}

// ---------------------------------------------------------------------------
// Pull aggregation + self-loop + bias: one warp per dst node.
// OUT[n] = sum_e dis[src]*dis[n] * H[src] + H[n]*dis[n]^2 + b
__global__ void k_agg(const float* __restrict__ H, float* __restrict__ OUT,
                      const float* __restrict__ b) {
    int node = (blockIdx.x * blockDim.x + threadIdx.x) >> 5;
    int lane = threadIdx.x & 31;
    if (node >= NN) return;

    int beg = __ldg(&g_rowptr[node]);
    int cnt = __ldg(&g_deg[node]);
    float disd = __ldg(&g_dis[node]);
    const int c = lane * 2;

    // self-loop init
    float2 hn = *(const float2*)&H[node * DD + c];
    float d2 = disd * disd;
    float ax = hn.x * d2, ay = hn.y * d2;

    int e = beg, end = beg + cnt;
    for (; e + 3 < end; e += 4) {
        int s0 = __ldg(&g_src[e]);
        int s1 = __ldg(&g_src[e + 1]);
        int s2 = __ldg(&g_src[e + 2]);
        int s3 = __ldg(&g_src[e + 3]);
        float w0 = __ldg(&g_dis[s0]) * disd;
        float w1 = __ldg(&g_dis[s1]) * disd;
        float w2 = __ldg(&g_dis[s2]) * disd;
        float w3 = __ldg(&g_dis[s3]) * disd;
        float2 h0 = *(const float2*)&H[s0 * DD + c];
        float2 h1 = *(const float2*)&H[s1 * DD + c];
        float2 h2 = *(const float2*)&H[s2 * DD + c];
        float2 h3 = *(const float2*)&H[s3 * DD + c];
        ax += w0 * h0.x + w1 * h1.x + w2 * h2.x + w3 * h3.x;
        ay += w0 * h0.y + w1 * h1.y + w2 * h2.y + w3 * h3.y;
    }
    for (; e < end; e++) {
        int s0 = __ldg(&g_src[e]);
        float w0 = __ldg(&g_dis[s0]) * disd;
        float2 h0 = *(const float2*)&H[s0 * DD + c];
        ax += w0 * h0.x;
        ay += w0 * h0.y;
    }

    float2 bv = *(const float2*)&b[c];
    float2 o;
    o.x = ax + bv.x;
    o.y = ay + bv.y;
    *(float2*)&OUT[node * DD + c] = o;
}

// ---------------------------------------------------------------------------
extern "C" void kernel_launch(void* const* d_in, const int* in_sizes, int n_in,
                              void* d_out, int out_size) {
    const float* x  = (const float*)d_in[0];
    const int*   ei = (const int*)d_in[1];
    const float* W1 = (const float*)d_in[2];
    const float* b1 = (const float*)d_in[3];
    const float* W2 = (const float*)d_in[4];
    const float* b2 = (const float*)d_in[5];
    float* out = (float*)d_out;

    float* dH;   cudaGetSymbolAddress((void**)&dH,   g_h);
    float* dBuf; cudaGetSymbolAddress((void**)&dBuf, g_buf);
    int*   dDeg; cudaGetSymbolAddress((void**)&dDeg, g_deg);
    int*   dCtr; cudaGetSymbolAddress((void**)&dCtr, g_ctr);

    const int TB = 256;
    const int gE4 = (EE / 4 + TB - 1) / TB;
    const int gG = (NN + 63) / 64;
    const int gA = (NN * 32 + TB - 1) / TB;   // warp per node

    // CSR setup (shared by both layers)
    cudaMemsetAsync(dDeg, 0, NN * sizeof(int));
    cudaMemsetAsync(dCtr, 0, sizeof(int));
    k_hist<<<gE4, TB>>>(ei);
    k_buckets<<<NB, 256>>>();
    k_build<<<gE4, TB>>>(ei);

    // Layer 1
    k_gemm<false><<<gG, TB>>>(x, W1, dH);
    k_agg<<<gA, TB>>>(dH, dBuf, b1);

    // Layer 2
    k_gemm<true><<<gG, TB>>>(dBuf, W2, dH);
    k_agg<<<gA, TB>>>(dH, out, b2);
}

// round 4
// speedup vs baseline: 1.4593x; 1.0423x over previous
#include <cuda_runtime.h>
#include <cuda_bf16.h>

#define NN 100000
#define EE 1000000
#define DD 64

#define SCAN_CHUNK 1024
#define NB ((NN + SCAN_CHUNK - 1) / SCAN_CHUNK)   // 98 blocks

// Scratch (device globals; no allocation allowed)
__device__ int   g_deg[NN];          // in-degree (excl self loop)
__device__ int   g_rowptr[NN];       // CSR bucket start (arrival-order bases)
__device__ float g_dis[NN];          // rsqrt(deg+1)
__device__ int   g_rank[EE];         // per-edge rank within dst bucket
__device__ int   g_src[EE];          // CSR: source node per slot
__device__ int   g_ctr;              // arrival-order base counter
__device__ float g_h[NN * DD];       // h = act(X) @ W
__device__ float g_buf[NN * DD];     // layer-1 output buffer
// Precomputed tf32 hi/lo W fragments, layout [s][j][lane][4] = {hi0,hi1,lo0,lo1}
__device__ float4 g_wf1[8 * 8 * 32];
__device__ float4 g_wf2[8 * 8 * 32];

// ---------------------------------------------------------------------------
__device__ __forceinline__ unsigned f2tf32(float x) {
    unsigned r;
    asm("cvt.rna.tf32.f32 %0, %1;" : "=r"(r) : "f"(x));
    return r;
}

// ---------------------------------------------------------------------------
// hist: rank[e] = deg[dst]++  (4 edges per thread, vectorized)
__global__ void k_hist(const int* __restrict__ ei) {
    int t = blockIdx.x * blockDim.x + threadIdx.x;
    int e = t * 4;
    if (e + 3 < EE) {
        int4 d = *(const int4*)&ei[EE + e];
        int4 r;
        r.x = atomicAdd(&g_deg[d.x], 1);
        r.y = atomicAdd(&g_deg[d.y], 1);
        r.z = atomicAdd(&g_deg[d.z], 1);
        r.w = atomicAdd(&g_deg[d.w], 1);
        *(int4*)&g_rank[e] = r;
    } else {
        for (; e < EE; e++) {
            int d = __ldg(&ei[EE + e]);
            g_rank[e] = atomicAdd(&g_deg[d], 1);
        }
    }
}

// ---------------------------------------------------------------------------
// one-kernel bucket assignment: block-local scan + atomic base (arrival order)
__global__ void k_buckets() {
    const int tid = threadIdx.x;
    const int base = blockIdx.x * SCAN_CHUNK;
    int v[4];
    int tsum = 0;
    #pragma unroll
    for (int j = 0; j < 4; j++) {
        int idx = base + tid * 4 + j;
        v[j] = (idx < NN) ? g_deg[idx] : 0;
        tsum += v[j];
    }
    int lane = tid & 31, wid = tid >> 5;
    int x = tsum;
    #pragma unroll
    for (int off = 1; off < 32; off <<= 1) {
        int y = __shfl_up_sync(0xFFFFFFFFu, x, off);
        if (lane >= off) x += y;
    }
    __shared__ int wsum[8], wofs[8];
    __shared__ int sbase;
    if (lane == 31) wsum[wid] = x;
    __syncthreads();
    if (tid == 0) {
        int run = 0;
        #pragma unroll
        for (int w = 0; w < 8; w++) { wofs[w] = run; run += wsum[w]; }
        sbase = atomicAdd(&g_ctr, run);
    }
    __syncthreads();
    int excl = sbase + wofs[wid] + (x - tsum);
    #pragma unroll
    for (int j = 0; j < 4; j++) {
        int idx = base + tid * 4 + j;
        if (idx < NN) {
            g_rowptr[idx] = excl;
            g_dis[idx] = rsqrtf((float)(v[j] + 1));
        }
        excl += v[j];
    }
}

// ---------------------------------------------------------------------------
// build (atomic-free): src[rowptr[dst] + rank[e]] = src_node
__global__ void k_build(const int* __restrict__ ei) {
    int t = blockIdx.x * blockDim.x + threadIdx.x;
    int e = t * 4;
    if (e + 3 < EE) {
        int4 s = *(const int4*)&ei[e];
        int4 d = *(const int4*)&ei[EE + e];
        int4 r = *(const int4*)&g_rank[e];
        g_src[__ldg(&g_rowptr[d.x]) + r.x] = s.x;
        g_src[__ldg(&g_rowptr[d.y]) + r.y] = s.y;
        g_src[__ldg(&g_rowptr[d.z]) + r.z] = s.z;
        g_src[__ldg(&g_rowptr[d.w]) + r.w] = s.w;
    } else {
        for (; e < EE; e++) {
            int s = __ldg(&ei[e]);
            int d = __ldg(&ei[EE + e]);
            g_src[__ldg(&g_rowptr[d]) + __ldg(&g_rank[e])] = s;
        }
    }
}

// ---------------------------------------------------------------------------
// Precompute W fragments in mma.m16n8k8 B-layout, tf32 hi/lo split.
// b0 = W[k=8s+(l&3)][n=8j+(l>>2)], b1 = same with k+4.
__global__ void k_wfrag(const float* __restrict__ W1, const float* __restrict__ W2) {
    int tid = threadIdx.x;
    for (int it = 0; it < 8; it++) {
        int idx = it * 256 + tid;              // [0, 2048)
        int s = idx >> 8;
        int j = (idx >> 5) & 7;
        int lane = idx & 31;
        int k0 = s * 8 + (lane & 3);
        int n  = j * 8 + (lane >> 2);
        {
            float w0 = W1[k0 * DD + n];
            float w1 = W1[(k0 + 4) * DD + n];
            unsigned h0 = f2tf32(w0), h1 = f2tf32(w1);
            unsigned l0 = f2tf32(w0 - __uint_as_float(h0));
            unsigned l1 = f2tf32(w1 - __uint_as_float(h1));
            float4 f;
            f.x = __uint_as_float(h0); f.y = __uint_as_float(h1);
            f.z = __uint_as_float(l0); f.w = __uint_as_float(l1);
            g_wf1[idx] = f;
        }
        {
            float w0 = W2[k0 * DD + n];
            float w1 = W2[(k0 + 4) * DD + n];
            unsigned h0 = f2tf32(w0), h1 = f2tf32(w1);
            unsigned l0 = f2tf32(w0 - __uint_as_float(h0));
            unsigned l1 = f2tf32(w1 - __uint_as_float(h1));
            float4 f;
            f.x = __uint_as_float(h0); f.y = __uint_as_float(h1);
            f.z = __uint_as_float(l0); f.w = __uint_as_float(l1);
            g_wf2[idx] = f;
        }
    }
}

// ---------------------------------------------------------------------------
#define MMA_TF32(C, A0, A1, A2, A3, B0, B1)                                   \
    asm volatile(                                                             \
        "mma.sync.aligned.m16n8k8.row.col.f32.tf32.tf32.f32 "                 \
        "{%0,%1,%2,%3}, {%4,%5,%6,%7}, {%8,%9}, {%0,%1,%2,%3};"               \
        : "+f"(C[0]), "+f"(C[1]), "+f"(C[2]), "+f"(C[3])                      \
        : "r"(A0), "r"(A1), "r"(A2), "r"(A3), "r"(B0), "r"(B1))

// Tensor-core GEMM: H = act(X) @ W, 3xTF32 (full fp32 accuracy).
// One warp per 16-row tile; A loaded directly from global (zero reuse),
// B from precomputed fragment table (L1-resident). No smem.
template <bool RELU_ON_LOAD>
__global__ void k_gemm_tc(const float* __restrict__ X, float* __restrict__ H,
                          const float4* __restrict__ WF) {
    const int warp = threadIdx.x >> 5;
    const int lane = threadIdx.x & 31;
    const int mtile = blockIdx.x * 8 + warp;       // 16-row tile
    if (mtile * 16 >= NN) return;                  // NN % 16 == 0

    const int row0 = mtile * 16 + (lane >> 2);
    const int row1 = row0 + 8;

    float acc[8][4];
    #pragma unroll
    for (int j = 0; j < 8; j++)
        #pragma unroll
        for (int q = 0; q < 4; q++) acc[j][q] = 0.0f;

    #pragma unroll
    for (int s = 0; s < 8; s++) {
        const int k0 = s * 8 + (lane & 3);
        float a0f = __ldg(&X[row0 * DD + k0]);
        float a1f = __ldg(&X[row1 * DD + k0]);
        float a2f = __ldg(&X[row0 * DD + k0 + 4]);
        float a3f = __ldg(&X[row1 * DD + k0 + 4]);
        if (RELU_ON_LOAD) {
            a0f = fmaxf(a0f, 0.0f); a1f = fmaxf(a1f, 0.0f);
            a2f = fmaxf(a2f, 0.0f); a3f = fmaxf(a3f, 0.0f);
        }
        unsigned ah0 = f2tf32(a0f), ah1 = f2tf32(a1f);
        unsigned ah2 = f2tf32(a2f), ah3 = f2tf32(a3f);
        unsigned al0 = f2tf32(a0f - __uint_as_float(ah0));
        unsigned al1 = f2tf32(a1f - __uint_as_float(ah1));
        unsigned al2 = f2tf32(a2f - __uint_as_float(ah2));
        unsigned al3 = f2tf32(a3f - __uint_as_float(ah3));

        #pragma unroll
        for (int j = 0; j < 8; j++) {
            float4 w = __ldg(&WF[(s * 8 + j) * 32 + lane]);
            unsigned bh0 = __float_as_uint(w.x);
            unsigned bh1 = __float_as_uint(w.y);
            unsigned bl0 = __float_as_uint(w.z);
            unsigned bl1 = __float_as_uint(w.w);
            MMA_TF32(acc[j], ah0, ah1, ah2, ah3, bh0, bh1);
            MMA_TF32(acc[j], al0, al1, al2, al3, bh0, bh1);
            MMA_TF32(acc[j], ah0, ah1, ah2, ah3, bl0, bl1);
        }
    }

    // epilogue: c0,c1 -> (row0, 2c..2c+1); c2,c3 -> (row1, ..)
    const int c = 2 * (lane & 3);
    #pragma unroll
    for (int j = 0; j < 8; j++) {
        float2 lo; lo.x = acc[j][0]; lo.y = acc[j][1];
        float2 hi; hi.x = acc[j][2]; hi.y = acc[j][3];
        *(float2*)&H[row0 * DD + j * 8 + c] = lo;
        *(float2*)&H[row1 * DD + j * 8 + c] = hi;
    }
}

// ---------------------------------------------------------------------------
// Pull aggregation + self-loop + bias: one warp per dst node.
__global__ void k_agg(const float* __restrict__ H, float* __restrict__ OUT,
                      const float* __restrict__ b) {
    int node = (blockIdx.x * blockDim.x + threadIdx.x) >> 5;
    int lane = threadIdx.x & 31;
    if (node >= NN) return;

    int beg = __ldg(&g_rowptr[node]);
    int cnt = __ldg(&g_deg[node]);
    float disd = __ldg(&g_dis[node]);
    const int c = lane * 2;

    float2 hn = *(const float2*)&H[node * DD + c];
    float d2 = disd * disd;
    float ax = hn.x * d2, ay = hn.y * d2;

    int e = beg, end = beg + cnt;
    for (; e + 3 < end; e += 4) {
        int s0 = __ldg(&g_src[e]);
        int s1 = __ldg(&g_src[e + 1]);
        int s2 = __ldg(&g_src[e + 2]);
        int s3 = __ldg(&g_src[e + 3]);
        float w0 = __ldg(&g_dis[s0]) * disd;
        float w1 = __ldg(&g_dis[s1]) * disd;
        float w2 = __ldg(&g_dis[s2]) * disd;
        float w3 = __ldg(&g_dis[s3]) * disd;
        float2 h0 = *(const float2*)&H[s0 * DD + c];
        float2 h1 = *(const float2*)&H[s1 * DD + c];
        float2 h2 = *(const float2*)&H[s2 * DD + c];
        float2 h3 = *(const float2*)&H[s3 * DD + c];
        ax += w0 * h0.x + w1 * h1.x + w2 * h2.x + w3 * h3.x;
        ay += w0 * h0.y + w1 * h1.y + w2 * h2.y + w3 * h3.y;
    }
    for (; e < end; e++) {
        int s0 = __ldg(&g_src[e]);
        float w0 = __ldg(&g_dis[s0]) * disd;
        float2 h0 = *(const float2*)&H[s0 * DD + c];
        ax += w0 * h0.x;
        ay += w0 * h0.y;
    }

    float2 bv = *(const float2*)&b[c];
    float2 o;
    o.x = ax + bv.x;
    o.y = ay + bv.y;
    *(float2*)&OUT[node * DD + c] = o;
}

// ---------------------------------------------------------------------------
extern "C" void kernel_launch(void* const* d_in, const int* in_sizes, int n_in,
                              void* d_out, int out_size) {
    const float* x  = (const float*)d_in[0];
    const int*   ei = (const int*)d_in[1];
    const float* W1 = (const float*)d_in[2];
    const float* b1 = (const float*)d_in[3];
    const float* W2 = (const float*)d_in[4];
    const float* b2 = (const float*)d_in[5];
    float* out = (float*)d_out;

    float*  dH;   cudaGetSymbolAddress((void**)&dH,   g_h);
    float*  dBuf; cudaGetSymbolAddress((void**)&dBuf, g_buf);
    int*    dDeg; cudaGetSymbolAddress((void**)&dDeg, g_deg);
    int*    dCtr; cudaGetSymbolAddress((void**)&dCtr, g_ctr);
    float4* dW1f; cudaGetSymbolAddress((void**)&dW1f, g_wf1);
    float4* dW2f; cudaGetSymbolAddress((void**)&dW2f, g_wf2);

    const int TB = 256;
    const int gE4 = (EE / 4 + TB - 1) / TB;
    const int gG = (NN / 16 + 7) / 8;         // 8 warps/block, 16 rows/warp
    const int gA = (NN * 32 + TB - 1) / TB;   // warp per node

    // CSR setup + W fragment precompute (shared by both layers)
    cudaMemsetAsync(dDeg, 0, NN * sizeof(int));
    cudaMemsetAsync(dCtr, 0, sizeof(int));
    k_wfrag<<<1, 256>>>(W1, W2);
    k_hist<<<gE4, TB>>>(ei);
    k_buckets<<<NB, 256>>>();
    k_build<<<gE4, TB>>>(ei);

    // Layer 1
    k_gemm_tc<false><<<gG, TB>>>(x, dH, dW1f);
    k_agg<<<gA, TB>>>(dH, dBuf, b1);

    // Layer 2
    k_gemm_tc<true><<<gG, TB>>>(dBuf, dH, dW2f);
    k_agg<<<gA, TB>>>(dH, out, b2);
}